// round 9
// baseline (speedup 1.0000x reference)
#include <cuda_runtime.h>
#include <math.h>

#define T_STEPS 8192
#define HID     1024
#define IN_K    2048
#define NGATE   3072
#define NCTA    128

// ---- device scratch (allocation-free: __device__ globals) ----
__device__ float g_gi[(size_t)T_STEPS * NGATE];      // ~100.7 MB precomputed input gates
__device__ float g_hv[2][HID];                        // double-buffered h
__device__ unsigned g_ctr;                            // monotonic step counter (release/acquire, GPU scope)

// =====================================================================
// Kernel 1: gi = features @ w_ih[:, :2048]^T + rewards * w_ih[:,2048] + b_ih
// fp32 SIMT tiled GEMM, BM=BN=128, BK=16, 8x8 per thread, 2 CTAs/SM.
// (R6 version, known good: ~2.9 ms.) Block (0,0) resets the scan counter.
// =====================================================================
#define BM 128
#define BN 128
#define BK 16

__global__ void __launch_bounds__(256, 2) gi_gemm(
    const float* __restrict__ feat,   // [8192, 2048]
    const float* __restrict__ rew,    // [8192]
    const float* __restrict__ w_ih,   // [3072, 2049]  (row stride 2049!)
    const float* __restrict__ b_ih)   // [3072]
{
    __shared__ float As[BK][BM];
    __shared__ float Ws[BK][BN];

    const int tid   = threadIdx.x;
    if (blockIdx.x == 0 && blockIdx.y == 0 && tid == 0) g_ctr = 0u;

    const int nBase = blockIdx.x * BN;
    const int mBase = blockIdx.y * BM;
    const int tx = tid & 15;          // n direction
    const int ty = tid >> 4;          // m direction

    float acc[8][8];
    #pragma unroll
    for (int i = 0; i < 8; i++)
        #pragma unroll
        for (int j = 0; j < 8; j++) acc[i][j] = 0.f;

    for (int kB = 0; kB < IN_K; kB += BK) {
        #pragma unroll
        for (int v = 0; v < 2; v++) {
            int f   = tid + v * 256;            // 0..511
            int row = f >> 2;
            int kq  = (f & 3) << 2;
            float4 a = *reinterpret_cast<const float4*>(
                &feat[(size_t)(mBase + row) * IN_K + kB + kq]);
            As[kq + 0][row] = a.x;
            As[kq + 1][row] = a.y;
            As[kq + 2][row] = a.z;
            As[kq + 3][row] = a.w;
        }
        #pragma unroll
        for (int v = 0; v < 8; v++) {
            int f   = tid + v * 256;            // 0..2047
            int row = f >> 4;
            int kk  = f & 15;
            Ws[kk][row] = w_ih[(size_t)(nBase + row) * 2049 + kB + kk];
        }
        __syncthreads();

        #pragma unroll
        for (int k = 0; k < BK; k++) {
            float a[8], b[8];
            float4 a0 = *reinterpret_cast<const float4*>(&As[k][ty * 8 + 0]);
            float4 a1 = *reinterpret_cast<const float4*>(&As[k][ty * 8 + 4]);
            float4 b0 = *reinterpret_cast<const float4*>(&Ws[k][tx * 8 + 0]);
            float4 b1 = *reinterpret_cast<const float4*>(&Ws[k][tx * 8 + 4]);
            a[0]=a0.x; a[1]=a0.y; a[2]=a0.z; a[3]=a0.w;
            a[4]=a1.x; a[5]=a1.y; a[6]=a1.z; a[7]=a1.w;
            b[0]=b0.x; b[1]=b0.y; b[2]=b0.z; b[3]=b0.w;
            b[4]=b1.x; b[5]=b1.y; b[6]=b1.z; b[7]=b1.w;
            #pragma unroll
            for (int i = 0; i < 8; i++)
                #pragma unroll
                for (int j = 0; j < 8; j++)
                    acc[i][j] = fmaf(a[i], b[j], acc[i][j]);
        }
        __syncthreads();
    }

    float rw[8], wl[8], bb[8];
    #pragma unroll
    for (int i = 0; i < 8; i++) rw[i] = rew[mBase + ty * 8 + i];
    #pragma unroll
    for (int j = 0; j < 8; j++) {
        int n = nBase + tx * 8 + j;
        wl[j] = w_ih[(size_t)n * 2049 + 2048];
        bb[j] = b_ih[n];
    }
    #pragma unroll
    for (int i = 0; i < 8; i++) {
        int m = mBase + ty * 8 + i;
        #pragma unroll
        for (int j = 0; j < 8; j++) {
            int n = nBase + tx * 8 + j;
            g_gi[(size_t)m * NGATE + n] = acc[i][j] + rw[i] * wl[j] + bb[j];
        }
    }
}

// =====================================================================
// Kernel 2: persistent GRU reverse scan, 128 CTAs x 288 threads.
// Warps 0-7: compute (unit u = 8c + w, weights in 96 regs/thread).
// Warp 8:   dedicated poller+stager. It acquire-polls the global counter
//           for epoch s, ld.cg-fetches h^s, stages into h_sm[s&1], and
//           bar.arrive(1,288). It then immediately polls for s+1 while
//           compute warps work on s (hides observe behind compute).
// Producers keep the proven R6 release pattern:
//           lane0 st.cg h -> bar.sync(2,256) -> thread0 red.release.gpu.
// Buffer safety: ctr >= 128*s  =>  all CTAs finished step s-1  =>  no one
// still reads h_sm/g_hv parity s&1 from step s-2 (two-generation argument).
// =====================================================================
__device__ __forceinline__ float sigmoidf_(float x)
{
    return __fdividef(1.f, 1.f + __expf(-x));
}
__device__ __forceinline__ float tanhf_(float x)
{
    float ax = fabsf(x);
    float e  = __expf(-2.f * ax);
    float t  = __fdividef(1.f - e, 1.f + e);
    return copysignf(t, x);
}

__global__ void __launch_bounds__(288, 1) gru_scan(
    const float* __restrict__ w_hh,   // [3072, 1024]
    const float* __restrict__ b_hh,   // [3072]
    float* __restrict__ out)          // [1024]
{
    __shared__ float h_sm[2][HID];

    const int tid = threadIdx.x;
    const int c = blockIdx.x;
    const int w = tid >> 5;           // 0..8
    const int l = tid & 31;

    // zero h_sm[0] (consumed at step 0); threads 0..255 cover it
    if (tid < 256) {
        float4 z4 = make_float4(0.f, 0.f, 0.f, 0.f);
        *reinterpret_cast<float4*>(&h_sm[0][tid * 4]) = z4;
    }
    __syncthreads();   // all 288 threads; only barrier of this kind

    unsigned* ctrp = &g_ctr;

    if (w == 8) {
        // ---------------- stager warp ----------------
        // initial arrival: buffer 0 is ready (zeros)
        asm volatile("bar.arrive 1, 288;" ::: "memory");
        for (int s = 1; s < T_STEPS; s++) {
            const unsigned target = (unsigned)s * (unsigned)NCTA;
            unsigned f0, f1;
            do {   // two overlapped polls per iteration (finer observe granularity)
                asm volatile("ld.acquire.gpu.global.u32 %0, [%2];\n\t"
                             "ld.acquire.gpu.global.u32 %1, [%2];"
                             : "=r"(f0), "=r"(f1) : "l"(ctrp) : "memory");
            } while (f0 < target && f1 < target);
            // stage h^s : 32 lanes x 8 float4 (coalesced), acquire orders these
            const float* vb = g_hv[s & 1];
            float* dst = h_sm[s & 1];
            #pragma unroll
            for (int q = 0; q < 8; q++) {
                const int idx = (q * 32 + l) * 4;
                float4 hv4;
                asm volatile("ld.global.cg.v4.f32 {%0,%1,%2,%3}, [%4];"
                             : "=f"(hv4.x), "=f"(hv4.y), "=f"(hv4.z), "=f"(hv4.w)
                             : "l"(vb + idx) : "memory");
                *reinterpret_cast<float4*>(dst + idx) = hv4;
            }
            asm volatile("bar.arrive 1, 288;" ::: "memory");
        }
        return;
    }

    // ---------------- compute warps (0..7) ----------------
    const int u = c * 8 + w;

    // register-resident recurrent weights: lane l holds k = l + 32j
    float wr[32], wz[32], wn[32];
    {
        const float* pr = w_hh + (size_t)(          u) * HID + l;
        const float* pz = w_hh + (size_t)(HID     + u) * HID + l;
        const float* pn = w_hh + (size_t)(2 * HID + u) * HID + l;
        #pragma unroll
        for (int j = 0; j < 32; j++) {
            wr[j] = pr[32 * j];
            wz[j] = pz[32 * j];
            wn[j] = pn[32 * j];
        }
    }
    const float bhr = b_hh[u];
    const float bhz = b_hh[HID + u];
    const float bhn = b_hh[2 * HID + u];

    float hval = 0.f;

    for (int s = 0; s < T_STEPS; s++) {
        const int t = T_STEPS - 1 - s;   // reverse scan
        // prefetch gi (independent of h -> in flight across the barrier wait)
        const float* gip = g_gi + (size_t)t * NGATE + u;
        const float gir = __ldg(gip);
        const float giz = __ldg(gip + HID);
        const float gin = __ldg(gip + 2 * HID);

        asm volatile("bar.sync 1, 288;" ::: "memory");   // h^s staged in h_sm[s&1]

        const float* hbuf = h_sm[s & 1];
        // three dots, 2-way split accumulators (16-deep chains)
        float dra = 0.f, drb = 0.f, dza = 0.f, dzb = 0.f, dna = 0.f, dnb = 0.f;
        #pragma unroll
        for (int j = 0; j < 32; j += 2) {
            const float ha = hbuf[l + 32 * j];
            const float hb = hbuf[l + 32 * (j + 1)];
            dra = fmaf(wr[j], ha, dra);  drb = fmaf(wr[j + 1], hb, drb);
            dza = fmaf(wz[j], ha, dza);  dzb = fmaf(wz[j + 1], hb, dzb);
            dna = fmaf(wn[j], ha, dna);  dnb = fmaf(wn[j + 1], hb, dnb);
        }
        float dr = dra + drb, dz = dza + dzb, dn = dna + dnb;
        #pragma unroll
        for (int o = 16; o > 0; o >>= 1) {
            dr += __shfl_xor_sync(0xffffffffu, dr, o);
            dz += __shfl_xor_sync(0xffffffffu, dz, o);
            dn += __shfl_xor_sync(0xffffffffu, dn, o);
        }

        const float r = sigmoidf_(gir + dr + bhr);
        const float z = sigmoidf_(giz + dz + bhz);
        const float n = tanhf_(gin + r * (dn + bhn));
        hval = (1.f - z) * n + z * hval;

        if (s < T_STEPS - 1) {
            if (l == 0)
                asm volatile("st.global.cg.f32 [%0], %1;"
                             :: "l"(&g_hv[(s + 1) & 1][u]), "f"(hval) : "memory");
            asm volatile("bar.sync 2, 256;" ::: "memory");   // publish drained, CTA-ordered
            if (tid == 0)
                asm volatile("red.release.gpu.global.add.u32 [%0], %1;"
                             :: "l"(ctrp), "r"(1u) : "memory");
        }
    }

    if (l == 0) out[u] = hval;
}

// =====================================================================
extern "C" void kernel_launch(void* const* d_in, const int* in_sizes, int n_in,
                              void* d_out, int out_size)
{
    const float* feat = (const float*)d_in[0];   // [8192, 2048]
    const float* rew  = (const float*)d_in[1];   // [8192]
    const float* w_ih = (const float*)d_in[2];   // [3072, 2049]
    const float* w_hh = (const float*)d_in[3];   // [3072, 1024]
    const float* b_ih = (const float*)d_in[4];   // [3072]
    const float* b_hh = (const float*)d_in[5];   // [3072]
    float* out = (float*)d_out;                  // [1, 1024]

    dim3 ggrid(NGATE / BN, T_STEPS / BM);        // (24, 64)
    gi_gemm<<<ggrid, 256>>>(feat, rew, w_ih, b_ih);
    gru_scan<<<NCTA, 288>>>(w_hh, b_hh, out);
}

// round 10
// speedup vs baseline: 1.5799x; 1.5799x over previous
#include <cuda_runtime.h>
#include <math.h>

#define T_STEPS 8192
#define HID     1024
#define IN_K    2048
#define NGATE   3072
#define NCTA    128

// ---- device scratch (allocation-free: __device__ globals) ----
__device__ float g_gi[(size_t)T_STEPS * NGATE];      // ~100.7 MB precomputed input gates
__device__ float g_wt[(size_t)NGATE * IN_K];          // 25 MB: w_ih[:, :2048] repacked, aligned stride 2048
__device__ float g_hv[2][HID];                        // double-buffered h
__device__ unsigned g_ctr;                            // monotonic step counter (release/acquire, GPU scope)

// =====================================================================
// Kernel 0: repack w_ih[:, :2048] (row stride 2049, misaligned) into
// g_wt (row stride 2048, float4-aligned). Also resets the scan counter.
// =====================================================================
__global__ void repack_w(const float* __restrict__ w_ih)
{
    if (blockIdx.x == 0 && threadIdx.x == 0) g_ctr = 0u;
    const size_t i = (size_t)blockIdx.x * blockDim.x + threadIdx.x;
    const size_t total = (size_t)NGATE * IN_K;
    for (size_t x = i; x < total; x += (size_t)gridDim.x * blockDim.x) {
        const size_t n = x >> 11;           // / 2048
        const size_t k = x & 2047;          // % 2048
        g_wt[x] = w_ih[n * 2049 + k];
    }
}

// =====================================================================
// Kernel 1: gi = features @ w_t^T + rewards * w_ih[:,2048] + b_ih
// fp32 SIMT tiled GEMM, BM=BN=128, BK=16, 8x8 per thread, 2 CTAs/SM.
// W tile now loads as float4 from the repacked g_wt (4x fewer LDG ops;
// the R1/R4 profiles showed L1/LSU 87% vs fma 42% -> LDG-issue-bound).
// =====================================================================
#define BM 128
#define BN 128
#define BK 16

__global__ void __launch_bounds__(256, 2) gi_gemm(
    const float* __restrict__ feat,   // [8192, 2048]
    const float* __restrict__ rew,    // [8192]
    const float* __restrict__ w_ih,   // [3072, 2049] (only col 2048 + epilogue use)
    const float* __restrict__ b_ih)   // [3072]
{
    __shared__ float As[BK][BM];
    __shared__ float Ws[BK][BN];

    const int tid   = threadIdx.x;
    const int nBase = blockIdx.x * BN;
    const int mBase = blockIdx.y * BM;
    const int tx = tid & 15;          // n direction
    const int ty = tid >> 4;          // m direction

    float acc[8][8];
    #pragma unroll
    for (int i = 0; i < 8; i++)
        #pragma unroll
        for (int j = 0; j < 8; j++) acc[i][j] = 0.f;

    for (int kB = 0; kB < IN_K; kB += BK) {
        // A tile: 512 float4, 2 per thread
        #pragma unroll
        for (int v = 0; v < 2; v++) {
            int f   = tid + v * 256;            // 0..511
            int row = f >> 2;
            int kq  = (f & 3) << 2;
            float4 a = *reinterpret_cast<const float4*>(
                &feat[(size_t)(mBase + row) * IN_K + kB + kq]);
            As[kq + 0][row] = a.x;
            As[kq + 1][row] = a.y;
            As[kq + 2][row] = a.z;
            As[kq + 3][row] = a.w;
        }
        // W tile: 512 float4, 2 per thread (aligned stride-2048 source)
        #pragma unroll
        for (int v = 0; v < 2; v++) {
            int f   = tid + v * 256;            // 0..511
            int row = f >> 2;
            int kq  = (f & 3) << 2;
            float4 b = *reinterpret_cast<const float4*>(
                &g_wt[(size_t)(nBase + row) * IN_K + kB + kq]);
            Ws[kq + 0][row] = b.x;
            Ws[kq + 1][row] = b.y;
            Ws[kq + 2][row] = b.z;
            Ws[kq + 3][row] = b.w;
        }
        __syncthreads();

        #pragma unroll
        for (int k = 0; k < BK; k++) {
            float a[8], b[8];
            float4 a0 = *reinterpret_cast<const float4*>(&As[k][ty * 8 + 0]);
            float4 a1 = *reinterpret_cast<const float4*>(&As[k][ty * 8 + 4]);
            float4 b0 = *reinterpret_cast<const float4*>(&Ws[k][tx * 8 + 0]);
            float4 b1 = *reinterpret_cast<const float4*>(&Ws[k][tx * 8 + 4]);
            a[0]=a0.x; a[1]=a0.y; a[2]=a0.z; a[3]=a0.w;
            a[4]=a1.x; a[5]=a1.y; a[6]=a1.z; a[7]=a1.w;
            b[0]=b0.x; b[1]=b0.y; b[2]=b0.z; b[3]=b0.w;
            b[4]=b1.x; b[5]=b1.y; b[6]=b1.z; b[7]=b1.w;
            #pragma unroll
            for (int i = 0; i < 8; i++)
                #pragma unroll
                for (int j = 0; j < 8; j++)
                    acc[i][j] = fmaf(a[i], b[j], acc[i][j]);
        }
        __syncthreads();
    }

    // epilogue: + rewards[m]*w_ih[n][2048] + b_ih[n]
    float rw[8], wl[8], bb[8];
    #pragma unroll
    for (int i = 0; i < 8; i++) rw[i] = rew[mBase + ty * 8 + i];
    #pragma unroll
    for (int j = 0; j < 8; j++) {
        int n = nBase + tx * 8 + j;
        wl[j] = w_ih[(size_t)n * 2049 + 2048];
        bb[j] = b_ih[n];
    }
    #pragma unroll
    for (int i = 0; i < 8; i++) {
        int m = mBase + ty * 8 + i;
        #pragma unroll
        for (int j = 0; j < 8; j++) {
            int n = nBase + tx * 8 + j;
            g_gi[(size_t)m * NGATE + n] = acc[i][j] + rw[i] * wl[j] + bb[j];
        }
    }
}

// =====================================================================
// Kernel 2: persistent GRU reverse scan (R6 protocol, the proven best).
// 128 CTAs x 256 threads. CTA c owns units [8c, 8c+8); warp w -> unit u.
// Only change vs R6: gi is prefetched ONE STEP AHEAD (registers), so the
// DRAM fetch has a full step (~3us) to land instead of just the poll gap.
// =====================================================================
__device__ __forceinline__ float sigmoidf_(float x)
{
    return __fdividef(1.f, 1.f + __expf(-x));
}
__device__ __forceinline__ float tanhf_(float x)
{
    float ax = fabsf(x);
    float e  = __expf(-2.f * ax);
    float t  = __fdividef(1.f - e, 1.f + e);
    return copysignf(t, x);
}

__global__ void __launch_bounds__(256, 1) gru_scan(
    const float* __restrict__ w_hh,   // [3072, 1024]
    const float* __restrict__ b_hh,   // [3072]
    float* __restrict__ out)          // [1024]
{
    __shared__ float h_sm[HID];

    const int tid = threadIdx.x;
    const int c = blockIdx.x;
    const int w = tid >> 5;
    const int l = tid & 31;
    const int u = c * 8 + w;

    // ---- register-resident recurrent weights: lane l holds k = l + 32j ----
    float wr[32], wz[32], wn[32];
    {
        const float* pr = w_hh + (size_t)(          u) * HID + l;
        const float* pz = w_hh + (size_t)(HID     + u) * HID + l;
        const float* pn = w_hh + (size_t)(2 * HID + u) * HID + l;
        #pragma unroll
        for (int j = 0; j < 32; j++) {
            wr[j] = pr[32 * j];
            wz[j] = pz[32 * j];
            wn[j] = pn[32 * j];
        }
    }
    const float bhr = b_hh[u];
    const float bhz = b_hh[HID + u];
    const float bhn = b_hh[2 * HID + u];

    // h^0 = 0
    {
        float4 z4 = make_float4(0.f, 0.f, 0.f, 0.f);
        *reinterpret_cast<float4*>(&h_sm[tid * 4]) = z4;
    }
    float hval = 0.f;   // this warp's unit value (h_prev[u])

    unsigned* ctrp = &g_ctr;

    // prefetch gi for step 0 (t = T-1)
    const float* gp0 = g_gi + (size_t)(T_STEPS - 1) * NGATE + u;
    float gir = __ldg(gp0), giz = __ldg(gp0 + HID), gin = __ldg(gp0 + 2 * HID);

    for (int s = 0; s < T_STEPS; s++) {
        const int t = T_STEPS - 1 - s;   // reverse scan
        // prefetch NEXT step's gi now: it has the whole step to complete
        float girN = 0.f, gizN = 0.f, ginN = 0.f;
        if (s + 1 < T_STEPS) {
            const float* gp = g_gi + (size_t)(t - 1) * NGATE + u;
            girN = __ldg(gp);
            gizN = __ldg(gp + HID);
            ginN = __ldg(gp + 2 * HID);
        }

        if (s > 0) {
            if (tid == 0) {
                // acquire-poll of the single counter word (GPU scope)
                const unsigned target = (unsigned)s * (unsigned)NCTA;
                unsigned f;
                do {
                    asm volatile("ld.acquire.gpu.global.u32 %0, [%1];"
                                 : "=r"(f) : "l"(ctrp) : "memory");
                } while (f < target);
            }
            __syncthreads();   // (A) barrier observed by all threads
            // cooperative fresh-h fetch (L2 only), 1 float4 per thread
            float4 hv4;
            asm volatile("ld.global.cg.v4.f32 {%0,%1,%2,%3}, [%4];"
                         : "=f"(hv4.x), "=f"(hv4.y), "=f"(hv4.z), "=f"(hv4.w)
                         : "l"(&g_hv[s & 1][tid * 4]) : "memory");
            *reinterpret_cast<float4*>(&h_sm[tid * 4]) = hv4;
        }
        __syncthreads();   // (B) h staged in smem

        // three 1024-dot-products for unit u, split over 32 lanes
        float dr = 0.f, dz = 0.f, dn = 0.f;
        #pragma unroll
        for (int j = 0; j < 32; j++) {
            const float h = h_sm[l + 32 * j];
            dr = fmaf(wr[j], h, dr);
            dz = fmaf(wz[j], h, dz);
            dn = fmaf(wn[j], h, dn);
        }
        #pragma unroll
        for (int o = 16; o > 0; o >>= 1) {
            dr += __shfl_xor_sync(0xffffffffu, dr, o);
            dz += __shfl_xor_sync(0xffffffffu, dz, o);
            dn += __shfl_xor_sync(0xffffffffu, dn, o);
        }

        const float r = sigmoidf_(gir + dr + bhr);
        const float z = sigmoidf_(giz + dz + bhz);
        const float n = tanhf_(gin + r * (dn + bhn));
        hval = (1.f - z) * n + z * hval;

        if (s < T_STEPS - 1) {
            if (l == 0)
                asm volatile("st.global.cg.f32 [%0], %1;"
                             :: "l"(&g_hv[(s + 1) & 1][u]), "f"(hval) : "memory");
            __syncthreads();   // (C) all 8 unit stores issued, CTA-ordered before release
            if (tid == 0)
                asm volatile("red.release.gpu.global.add.u32 [%0], %1;"
                             :: "l"(ctrp), "r"(1u) : "memory");
        }

        gir = girN; giz = gizN; gin = ginN;
    }

    if (l == 0) out[u] = hval;
}

// =====================================================================
extern "C" void kernel_launch(void* const* d_in, const int* in_sizes, int n_in,
                              void* d_out, int out_size)
{
    const float* feat = (const float*)d_in[0];   // [8192, 2048]
    const float* rew  = (const float*)d_in[1];   // [8192]
    const float* w_ih = (const float*)d_in[2];   // [3072, 2049]
    const float* w_hh = (const float*)d_in[3];   // [3072, 1024]
    const float* b_ih = (const float*)d_in[4];   // [3072]
    const float* b_hh = (const float*)d_in[5];   // [3072]
    float* out = (float*)d_out;                  // [1, 1024]

    repack_w<<<592, 256>>>(w_ih);                // ~10us: align W for float4 loads
    dim3 ggrid(NGATE / BN, T_STEPS / BM);        // (24, 64)
    gi_gemm<<<ggrid, 256>>>(feat, rew, w_ih, b_ih);
    gru_scan<<<NCTA, 256>>>(w_hh, b_hh, out);
}